// round 15
// baseline (speedup 1.0000x reference)
#include <cuda_runtime.h>
#include <cstdint>
#include <cstddef>

// Problem dims
#define T_STEPS 256
#define B_DIM   512
#define E_DIM   256
#define A_DIM   7
#define M_DIM   200
#define S_DIM   30
#define H_DIM   200
#define EA_DIM  263
#define G3      600
#define TB      131072   // T*B

typedef unsigned long long ull;

// Scratch (static device arrays: allocation-free rule)
__device__ float g_X[(size_t)TB * 200];   // X, later reused as P1
__device__ float g_GX[(size_t)TB * 600];  // precomputed input-side GRU gates
__device__ unsigned int g_flags[128];     // per-block epoch flags (scan barrier)

__device__ __forceinline__ float elu_f(float x) { return x > 0.f ? x : expm1f(x); }
__device__ __forceinline__ float sigm_f(float x) { return 1.f / (1.f + expf(-x)); }

// Packed f32x2 helpers (scan only)
__device__ __forceinline__ void fma2(ull& d, ull a, ull b) {
    asm("fma.rn.f32x2 %0, %1, %2, %3;" : "=l"(d) : "l"(a), "l"(b), "l"(d));
}
__device__ __forceinline__ ull pack2(float x, float y) {
    ull r;
    asm("mov.b64 %0, {%1, %2};" : "=l"(r)
        : "r"(__float_as_uint(x)), "r"(__float_as_uint(y)));
    return r;
}
__device__ __forceinline__ void unpack2(ull v, float& lo, float& hi) {
    unsigned int a, b;
    asm("mov.b64 {%0, %1}, %2;" : "=r"(a), "=r"(b) : "l"(v));
    lo = __uint_as_float(a); hi = __uint_as_float(b);
}

// ---------------------------------------------------------------------------
// Tiled GEMM (R13 shape, SCALAR inner loop): BM=128, BN=64, BK=16, 256 thr,
// occ 3, 2-stage smem double buffer, 8x4 scalar microtile. No forced 64-bit
// register pairing -> ptxas free bank allocation (banking-conflict theory).
// ---------------------------------------------------------------------------
#define GBM 128
#define GBN 64
#define GBK 16
#define ASTR 132
#define WSTR 68

template<int CONCAT>
__device__ __forceinline__ float4 loadA4(const float* __restrict__ A,
                                         const float* __restrict__ A2,
                                         size_t row, int k, int K, int KS)
{
    float4 v = make_float4(0.f, 0.f, 0.f, 0.f);
    if (CONCAT) {
        if (k + 3 < KS) {
            v = *(const float4*)(A + row * (size_t)KS + k);
        } else {
            float* pv = (float*)&v;
#pragma unroll
            for (int c = 0; c < 4; c++) {
                int kk = k + c;
                if (kk < KS)      pv[c] = A[row * (size_t)KS + kk];
                else if (kk < K)  pv[c] = A2[row * (size_t)(K - KS) + (kk - KS)];
            }
        }
    } else {
        if (k + 3 < K) {
            v = *(const float4*)(A + row * (size_t)K + k);
        } else {
            float* pv = (float*)&v;
#pragma unroll
            for (int c = 0; c < 4; c++)
                if (k + c < K) pv[c] = A[row * (size_t)K + k + c];
        }
    }
    return v;
}

__device__ __forceinline__ float4 loadW4(const float* __restrict__ W,
                                         int gn, int k, int K, int N)
{
    float4 v = make_float4(0.f, 0.f, 0.f, 0.f);
    if (gn < N) {
        if ((K & 3) == 0 && k + 3 < K) {
            v = *(const float4*)(W + (size_t)gn * (size_t)K + k);
        } else {
            float* pv = (float*)&v;
#pragma unroll
            for (int c = 0; c < 4; c++)
                if (k + c < K) pv[c] = W[(size_t)gn * (size_t)K + k + c];
        }
    }
    return v;
}

template<int ACT, int CONCAT>
__global__ __launch_bounds__(256, 3) void gemm_kernel(
    const float* __restrict__ A, const float* __restrict__ A2,
    int K, int KS,
    const float* __restrict__ W, const float* __restrict__ bias,
    float* __restrict__ C, int N)
{
    __shared__ float As[2][GBK * ASTR];
    __shared__ float Ws[2][GBK * WSTR];

    const int row0 = blockIdx.x * GBM;
    const int col0 = blockIdx.y * GBN;
    const int tid = threadIdx.x;
    const int tx = tid & 15;
    const int ty = tid >> 4;
    const int kq = tid & 3;
    const int rA = tid >> 2;

    float acc[8][4];
#pragma unroll
    for (int i = 0; i < 8; i++)
#pragma unroll
        for (int j = 0; j < 4; j++) acc[i][j] = 0.f;

    float4 la0, la1, lw;
    const int nT = (K + GBK - 1) / GBK;

    la0 = loadA4<CONCAT>(A, A2, (size_t)(row0 + rA),      kq * 4, K, KS);
    la1 = loadA4<CONCAT>(A, A2, (size_t)(row0 + rA + 64), kq * 4, K, KS);
    lw  = loadW4(W, col0 + rA, kq * 4, K, N);
    {
        As[0][(kq * 4 + 0) * ASTR + rA]      = la0.x;
        As[0][(kq * 4 + 1) * ASTR + rA]      = la0.y;
        As[0][(kq * 4 + 2) * ASTR + rA]      = la0.z;
        As[0][(kq * 4 + 3) * ASTR + rA]      = la0.w;
        As[0][(kq * 4 + 0) * ASTR + rA + 64] = la1.x;
        As[0][(kq * 4 + 1) * ASTR + rA + 64] = la1.y;
        As[0][(kq * 4 + 2) * ASTR + rA + 64] = la1.z;
        As[0][(kq * 4 + 3) * ASTR + rA + 64] = la1.w;
        Ws[0][(kq * 4 + 0) * WSTR + rA] = lw.x;
        Ws[0][(kq * 4 + 1) * WSTR + rA] = lw.y;
        Ws[0][(kq * 4 + 2) * WSTR + rA] = lw.z;
        Ws[0][(kq * 4 + 3) * WSTR + rA] = lw.w;
    }
    __syncthreads();

    int p = 0;
    for (int t = 0; t < nT; t++) {
        if (t + 1 < nT) {
            int k = (t + 1) * GBK + kq * 4;
            la0 = loadA4<CONCAT>(A, A2, (size_t)(row0 + rA),      k, K, KS);
            la1 = loadA4<CONCAT>(A, A2, (size_t)(row0 + rA + 64), k, K, KS);
            lw  = loadW4(W, col0 + rA, k, K, N);
        }

        const float* Ab = As[p];
        const float* Wb = Ws[p];
#pragma unroll
        for (int kk = 0; kk < GBK; kk++) {
            const float2* ap = (const float2*)(Ab + kk * ASTR + ty * 8);
            float a[8];
#pragma unroll
            for (int i = 0; i < 4; i++) {
                float2 t2 = ap[i];
                a[2 * i]     = t2.x;
                a[2 * i + 1] = t2.y;
            }
            const float4 wv = *(const float4*)(Wb + kk * WSTR + tx * 4);
            float w[4] = {wv.x, wv.y, wv.z, wv.w};
#pragma unroll
            for (int i = 0; i < 8; i++)
#pragma unroll
                for (int j = 0; j < 4; j++)
                    acc[i][j] = fmaf(a[i], w[j], acc[i][j]);
        }

        if (t + 1 < nT) {
            int s = p ^ 1;
            As[s][(kq * 4 + 0) * ASTR + rA]      = la0.x;
            As[s][(kq * 4 + 1) * ASTR + rA]      = la0.y;
            As[s][(kq * 4 + 2) * ASTR + rA]      = la0.z;
            As[s][(kq * 4 + 3) * ASTR + rA]      = la0.w;
            As[s][(kq * 4 + 0) * ASTR + rA + 64] = la1.x;
            As[s][(kq * 4 + 1) * ASTR + rA + 64] = la1.y;
            As[s][(kq * 4 + 2) * ASTR + rA + 64] = la1.z;
            As[s][(kq * 4 + 3) * ASTR + rA + 64] = la1.w;
            Ws[s][(kq * 4 + 0) * WSTR + rA] = lw.x;
            Ws[s][(kq * 4 + 1) * WSTR + rA] = lw.y;
            Ws[s][(kq * 4 + 2) * WSTR + rA] = lw.z;
            Ws[s][(kq * 4 + 3) * WSTR + rA] = lw.w;
            __syncthreads();
        }
        p ^= 1;
    }

    const int gc0 = col0 + tx * 4;
    float bv[4];
#pragma unroll
    for (int j = 0; j < 4; j++) bv[j] = (gc0 + j < N) ? bias[gc0 + j] : 0.f;

#pragma unroll
    for (int i = 0; i < 8; i++) {
        float v[4];
#pragma unroll
        for (int j = 0; j < 4; j++) {
            float x = acc[i][j] + bv[j];
            if (ACT) x = elu_f(x);
            v[j] = x;
        }
        size_t gr = (size_t)(row0 + ty * 8 + i);
        if (gc0 + 3 < N) {
            *(float4*)(C + gr * (size_t)N + gc0) = make_float4(v[0], v[1], v[2], v[3]);
        } else {
#pragma unroll
            for (int j = 0; j < 4; j++)
                if (gc0 + j < N) C[gr * (size_t)N + gc0 + j] = v[j];
        }
    }
}

// ---------------------------------------------------------------------------
// Recurrent scan v2 (unchanged from R10/R13).
// ---------------------------------------------------------------------------
#define SC_C   8
#define SC_R   16
#define SC_MC  25
#define SC_BC  32
#define SC_ROWS  75
#define SC_ROWSP 80
#define SC_HSTR  202
#define SC_GSTR  34
#define SC_THREADS 256
#define SC_SMEM_FLOATS (SC_ROWSP*200 + SC_BC*SC_HSTR + SC_ROWSP*SC_GSTR + G3)

__global__ void init_flags_kernel() { g_flags[threadIdx.x] = 0u; }

__global__ __launch_bounds__(SC_THREADS) void scan_kernel(
    const float* __restrict__ GX, const float* __restrict__ Whh,
    const float* __restrict__ bhh, const float* __restrict__ in_state,
    const unsigned char* __restrict__ reset, float* __restrict__ states)
{
    extern __shared__ float sm[];
    float* sW  = sm;                            // [80][200]  Whh slice
    float* sH  = sW + SC_ROWSP * 200;           // [32][202]  h (stride 202)
    float* sGH = sH + SC_BC * SC_HSTR;          // [80][34]   gh results
    float* sBH = sGH + SC_ROWSP * SC_GSTR;      // [600]      bhh

    const int c   = blockIdx.x & 7;
    const int r   = blockIdx.x >> 3;
    const int tid = threadIdx.x;
    const int rg  = tid >> 4;   // 0..15 -> 5 gh-rows each
    const int bg  = tid & 15;   // 0..15 -> 2 batch cols each

    for (int idx = tid; idx < SC_ROWSP * 200; idx += SC_THREADS) {
        int lr = idx / 200, k = idx % 200;
        float v = 0.f;
        if (lr < SC_ROWS) {
            int g = lr / SC_MC, j = lr % SC_MC;
            int grow = g * 200 + c * SC_MC + j;
            v = Whh[(size_t)grow * 200 + k];
        }
        sW[idx] = v;
    }
    for (int idx = tid; idx < G3; idx += SC_THREADS) sBH[idx] = bhh[idx];

    float pxr[4], pxz[4], pxn[4];
#pragma unroll
    for (int q = 0; q < 4; q++) {
        int idx = tid + q * SC_THREADS;
        if (idx < SC_MC * SC_BC) {
            int bl = idx / SC_MC, j = idx % SC_MC;
            int b = r * SC_BC + bl;
            int m = c * SC_MC + j;
            size_t gxi = (size_t)b * G3 + m;
            pxr[q] = GX[gxi];
            pxz[q] = GX[gxi + 200];
            pxn[q] = GX[gxi + 400];
        } else { pxr[q] = pxz[q] = pxn[q] = 0.f; }
    }

    for (int t = 0; t < T_STEPS; t++) {
        const float* hsrc = (t == 0) ? in_state
                                     : (states + (size_t)(t - 1) * B_DIM * M_DIM);
        for (int idx = tid; idx < SC_BC * 100; idx += SC_THREADS) {
            int bl = idx / 100, kp = idx % 100;
            int b = r * SC_BC + bl;
            ull v = *(const ull*)(hsrc + (size_t)b * 200 + kp * 2);
            if (reset[t * B_DIM + b]) v = 0ull;
            *(ull*)(sH + bl * SC_HSTR + kp * 2) = v;
        }
        __syncthreads();

        ull acc[5][2];
#pragma unroll
        for (int i = 0; i < 5; i++) { acc[i][0] = 0ull; acc[i][1] = 0ull; }

        const float* hb0 = sH + (bg * 2) * SC_HSTR;
        const float* hb1 = hb0 + SC_HSTR;
#pragma unroll 2
        for (int k = 0; k < 200; k += 4) {
            ull w0[5], w1[5];
#pragma unroll
            for (int i = 0; i < 5; i++) {
                const ull* wp = (const ull*)(sW + (rg * 5 + i) * 200 + k);
                w0[i] = wp[0]; w1[i] = wp[1];
            }
            ull h00 = *(const ull*)(hb0 + k);
            ull h01 = *(const ull*)(hb0 + k + 2);
            ull h10 = *(const ull*)(hb1 + k);
            ull h11 = *(const ull*)(hb1 + k + 2);
#pragma unroll
            for (int i = 0; i < 5; i++) {
                fma2(acc[i][0], w0[i], h00);
                fma2(acc[i][0], w1[i], h01);
                fma2(acc[i][1], w0[i], h10);
                fma2(acc[i][1], w1[i], h11);
            }
        }
#pragma unroll
        for (int i = 0; i < 5; i++) {
            float l0, h0, l1, h1;
            unpack2(acc[i][0], l0, h0);
            unpack2(acc[i][1], l1, h1);
            *(ull*)(sGH + (rg * 5 + i) * SC_GSTR + bg * 2) =
                pack2(l0 + h0, l1 + h1);
        }
        __syncthreads();

#pragma unroll
        for (int q = 0; q < 4; q++) {
            int idx = tid + q * SC_THREADS;
            if (idx < SC_MC * SC_BC) {
                int bl = idx / SC_MC, j = idx % SC_MC;
                int b = r * SC_BC + bl;
                int m = c * SC_MC + j;
                float hr = sGH[j * SC_GSTR + bl]               + sBH[m];
                float hz = sGH[(SC_MC + j) * SC_GSTR + bl]     + sBH[200 + m];
                float hn = sGH[(2 * SC_MC + j) * SC_GSTR + bl] + sBH[400 + m];
                float rgate = sigm_f(pxr[q] + hr);
                float z     = sigm_f(pxz[q] + hz);
                float n     = tanhf(pxn[q] + rgate * hn);
                float hp    = sH[bl * SC_HSTR + m];
                float hnew  = (1.f - z) * n + z * hp;
                states[(size_t)t * B_DIM * M_DIM + (size_t)b * M_DIM + m] = hnew;
            }
        }

        if (t + 1 < T_STEPS) {
            __syncthreads();
            if (tid == 0) {
                asm volatile("st.release.gpu.global.u32 [%0], %1;"
                             :: "l"(g_flags + blockIdx.x), "r"((unsigned)(t + 1))
                             : "memory");
            }
            size_t gbase = (size_t)((t + 1) * B_DIM) * G3;
#pragma unroll
            for (int q = 0; q < 4; q++) {
                int idx = tid + q * SC_THREADS;
                if (idx < SC_MC * SC_BC) {
                    int bl = idx / SC_MC, j = idx % SC_MC;
                    int b = r * SC_BC + bl;
                    int m = c * SC_MC + j;
                    size_t gxi = gbase + (size_t)b * G3 + m;
                    pxr[q] = GX[gxi];
                    pxz[q] = GX[gxi + 200];
                    pxn[q] = GX[gxi + 400];
                }
            }
            if (tid < SC_C) {
                const unsigned int* fp = g_flags + (r << 3) + tid;
                unsigned int v;
                do {
                    asm volatile("ld.acquire.gpu.global.u32 %0, [%1];"
                                 : "=r"(v) : "l"(fp) : "memory");
                } while (v < (unsigned)(t + 1));
            }
            __syncthreads();
        }
    }
}

// ---------------------------------------------------------------------------
// Sample head: partitionable threefry (counter = linear index), bits = o0^o1.
// ---------------------------------------------------------------------------
__global__ void sample_kernel(const float* __restrict__ posts_last,
                              float* __restrict__ out)
{
    int i = blockIdx.x * blockDim.x + threadIdx.x;
    const int NTOT = B_DIM * S_DIM;
    if (i >= NTOT) return;

    uint32_t x0 = 0u, x1 = (uint32_t)i;
    const uint32_t ks0 = 0u, ks1 = 42u, ks2 = 0u ^ 42u ^ 0x1BD11BDAu;
    x0 += ks0; x1 += ks1;
#define TF_RND(rot) { x0 += x1; x1 = (x1 << (rot)) | (x1 >> (32 - (rot))); x1 ^= x0; }
    TF_RND(13) TF_RND(15) TF_RND(26) TF_RND(6)   x0 += ks1; x1 += ks2 + 1u;
    TF_RND(17) TF_RND(29) TF_RND(16) TF_RND(24)  x0 += ks2; x1 += ks0 + 2u;
    TF_RND(13) TF_RND(15) TF_RND(26) TF_RND(6)   x0 += ks0; x1 += ks1 + 3u;
    TF_RND(17) TF_RND(29) TF_RND(16) TF_RND(24)  x0 += ks1; x1 += ks2 + 4u;
    TF_RND(13) TF_RND(15) TF_RND(26) TF_RND(6)   x0 += ks2; x1 += ks0 + 5u;
#undef TF_RND
    uint32_t bits = x0 ^ x1;

    float f = __uint_as_float((bits >> 9) | 0x3F800000u) - 1.0f;
    const float lo = -0.99999994f;
    float u = fmaxf(lo, f * 2.0f + lo);
    float noise = 1.41421356f * erfinvf(u);

    int b = i / S_DIM, s = i % S_DIM;
    float mean = posts_last[(size_t)b * 60 + s];
    float sraw = posts_last[(size_t)b * 60 + 30 + s];
    float stdv = fmaxf(sraw, 0.f) + log1pf(expf(-fabsf(sraw))) + 0.1f;
    out[i] = mean + stdv * noise;
}

// ---------------------------------------------------------------------------
extern "C" void kernel_launch(void* const* d_in, const int* in_sizes, int n_in,
                              void* d_out, int out_size)
{
    const float* embed    = (const float*)d_in[0];
    const float* action   = (const float*)d_in[1];
    const unsigned char* reset = (const unsigned char*)d_in[2];
    const float* in_state = (const float*)d_in[3];
    const float* W1 = (const float*)d_in[4];
    const float* b1 = (const float*)d_in[5];
    const float *Wih, *bih, *Whh, *bhh;
    if (in_sizes[7] == 600) {          // dict order: Wih, bih, Whh, bhh
        Wih = (const float*)d_in[6]; bih = (const float*)d_in[7];
        Whh = (const float*)d_in[8]; bhh = (const float*)d_in[9];
    } else {                           // signature order: Wih, Whh, bih, bhh
        Wih = (const float*)d_in[6]; Whh = (const float*)d_in[7];
        bih = (const float*)d_in[8]; bhh = (const float*)d_in[9];
    }
    const float* W2 = (const float*)d_in[10];
    const float* b2 = (const float*)d_in[11];
    const float* W3 = (const float*)d_in[12];
    const float* b3 = (const float*)d_in[13];

    float* out    = (float*)d_out;
    float* sample = out;                                  // [512,30]
    float* states = out + (size_t)B_DIM * S_DIM;          // [256,512,200]
    float* posts  = states + (size_t)T_STEPS * B_DIM * M_DIM; // [256,512,60]

    float* Xbuf; cudaGetSymbolAddress((void**)&Xbuf, g_X);
    float* GXbuf; cudaGetSymbolAddress((void**)&GXbuf, g_GX);

    // K1: X = elu([embed,action] @ W1^T + b1)   [131072,263]x[263,200]
    gemm_kernel<1, 1><<<dim3(TB / GBM, 4), 256>>>(
        embed, action, EA_DIM, E_DIM, W1, b1, Xbuf, H_DIM);

    // K2: GX = X @ Wih^T + bih                  [131072,200]x[200,600]
    gemm_kernel<0, 0><<<dim3(TB / GBM, 10), 256>>>(
        Xbuf, nullptr, H_DIM, 0, Wih, bih, GXbuf, G3);

    // K3: recurrent scan -> states
    init_flags_kernel<<<1, 128>>>();
    cudaFuncSetAttribute(scan_kernel,
                         cudaFuncAttributeMaxDynamicSharedMemorySize,
                         SC_SMEM_FLOATS * (int)sizeof(float));
    scan_kernel<<<SC_C * SC_R, SC_THREADS, SC_SMEM_FLOATS * sizeof(float)>>>(
        GXbuf, Whh, bhh, in_state, reset, states);

    // K4: P1 = elu(states @ W2^T + b2)  (reuse g_X)
    gemm_kernel<1, 0><<<dim3(TB / GBM, 4), 256>>>(
        states, nullptr, M_DIM, 0, W2, b2, Xbuf, H_DIM);

    // K5: posts = P1 @ W3^T + b3
    gemm_kernel<0, 0><<<dim3(TB / GBM, 1), 256>>>(
        Xbuf, nullptr, H_DIM, 0, W3, b3, posts, 2 * S_DIM);

    // K6: sample from posts[-1] with partitionable-threefry noise
    const float* posts_last = posts + (size_t)(T_STEPS - 1) * B_DIM * 2 * S_DIM;
    sample_kernel<<<(B_DIM * S_DIM + 255) / 256, 256>>>(posts_last, sample);
}

// round 16
// speedup vs baseline: 1.0789x; 1.0789x over previous
#include <cuda_runtime.h>
#include <cuda_bf16.h>
#include <cstdint>
#include <cstddef>

// Problem dims
#define T_STEPS 256
#define B_DIM   512
#define E_DIM   256
#define A_DIM   7
#define M_DIM   200
#define S_DIM   30
#define H_DIM   200
#define EA_DIM  263
#define G3      600
#define TB      131072   // T*B

typedef unsigned long long ull;
typedef unsigned short u16;

// bf16 operand buffers (hi/lo split), padded K dims: EA->288, X/S/P1->224
#define KP_EA 288
#define KP_X  224

__device__ float g_GX[(size_t)TB * 600];
__device__ unsigned int g_flags[128];

__device__ u16 g_EAhi[(size_t)TB * KP_EA];
__device__ u16 g_EAlo[(size_t)TB * KP_EA];   // later reused for P1 (stride 224)
__device__ u16 g_Xhi[(size_t)TB * KP_X];
__device__ u16 g_Xlo[(size_t)TB * KP_X];
__device__ u16 g_Shi[(size_t)TB * KP_X];
__device__ u16 g_Slo[(size_t)TB * KP_X];
// weights (rows padded to multiple of 128)
__device__ u16 g_W1h[256 * KP_EA], g_W1l[256 * KP_EA];
__device__ u16 g_Wih_h[640 * KP_X], g_Wih_l[640 * KP_X];
__device__ u16 g_W2h[256 * KP_X], g_W2l[256 * KP_X];
__device__ u16 g_W3h[128 * KP_X], g_W3l[128 * KP_X];

__device__ __forceinline__ float elu_f(float x) { return x > 0.f ? x : expm1f(x); }
__device__ __forceinline__ float sigm_f(float x) { return 1.f / (1.f + expf(-x)); }

__device__ __forceinline__ void split_bf(float f, u16& h, u16& l) {
    __nv_bfloat16 hb = __float2bfloat16_rn(f);
    float r = f - __bfloat162float(hb);
    h = __bfloat16_as_ushort(hb);
    l = __bfloat16_as_ushort(__float2bfloat16_rn(r));
}

// Packed f32x2 helpers (scan only)
__device__ __forceinline__ void fma2(ull& d, ull a, ull b) {
    asm("fma.rn.f32x2 %0, %1, %2, %3;" : "=l"(d) : "l"(a), "l"(b), "l"(d));
}
__device__ __forceinline__ ull pack2(float x, float y) {
    ull r;
    asm("mov.b64 %0, {%1, %2};" : "=l"(r)
        : "r"(__float_as_uint(x)), "r"(__float_as_uint(y)));
    return r;
}
__device__ __forceinline__ void unpack2(ull v, float& lo, float& hi) {
    unsigned int a, b;
    asm("mov.b64 {%0, %1}, %2;" : "=r"(a), "=r"(b) : "l"(v));
    lo = __uint_as_float(a); hi = __uint_as_float(b);
}

__device__ __forceinline__ uint32_t smem_u32(const void* p) {
    uint32_t a;
    asm("{ .reg .u64 t; cvta.to.shared.u64 t, %1; cvt.u32.u64 %0, t; }"
        : "=r"(a) : "l"(p));
    return a;
}
__device__ __forceinline__ void ldm_x4(uint32_t& r0, uint32_t& r1,
                                       uint32_t& r2, uint32_t& r3, uint32_t addr) {
    asm volatile("ldmatrix.sync.aligned.m8n8.x4.shared.b16 {%0,%1,%2,%3}, [%4];"
                 : "=r"(r0), "=r"(r1), "=r"(r2), "=r"(r3) : "r"(addr));
}
__device__ __forceinline__ void mma_bf16(float* c,
                                         uint32_t a0, uint32_t a1, uint32_t a2, uint32_t a3,
                                         uint32_t b0, uint32_t b1) {
    asm volatile("mma.sync.aligned.m16n8k16.row.col.f32.bf16.bf16.f32 "
                 "{%0,%1,%2,%3},{%4,%5,%6,%7},{%8,%9},{%0,%1,%2,%3};"
                 : "+f"(c[0]), "+f"(c[1]), "+f"(c[2]), "+f"(c[3])
                 : "r"(a0), "r"(a1), "r"(a2), "r"(a3), "r"(b0), "r"(b1));
}

// ---------------------------------------------------------------------------
// Converters (run once per operand)
// ---------------------------------------------------------------------------
__global__ void cvt_ea_kernel(const float* __restrict__ embed,
                              const float* __restrict__ action)
{
    size_t idx = (size_t)blockIdx.x * blockDim.x + threadIdx.x;
    if (idx >= (size_t)TB * KP_EA) return;
    int row = (int)(idx / KP_EA), col = (int)(idx % KP_EA);
    float f = 0.f;
    if (col < E_DIM)        f = embed[(size_t)row * E_DIM + col];
    else if (col < EA_DIM)  f = action[(size_t)row * A_DIM + (col - E_DIM)];
    u16 h, l; split_bf(f, h, l);
    g_EAhi[idx] = h; g_EAlo[idx] = l;
}

__global__ void cvt_w_kernel(const float* __restrict__ W, int N, int K,
                             int Kp, int Np, u16* __restrict__ Wh,
                             u16* __restrict__ Wl)
{
    int idx = blockIdx.x * blockDim.x + threadIdx.x;
    if (idx >= Np * Kp) return;
    int r = idx / Kp, k = idx % Kp;
    float f = (r < N && k < K) ? W[(size_t)r * K + k] : 0.f;
    u16 h, l; split_bf(f, h, l);
    Wh[idx] = h; Wl[idx] = l;
}

// ---------------------------------------------------------------------------
// Pipelined BF16 mma GEMM with 3-term split as K-concatenation:
//   C = Ahi*Bhi + Ahi*Blo + Alo*Bhi   over K' = 3*Kp (segment select per tile)
// Block 128x128, BK=32, 256 threads = 8 warps (2M x 4N), warp tile 64x32.
// smem stride 40 elems (80B): 16B-aligned, conflict-free ldmatrix.
// EMIT=1: write bf16 hi/lo (stride CKp) with act; EMIT=0: write fp32 C.
// ---------------------------------------------------------------------------
#define MM_STR 40
#define MM_STAGE (256 * MM_STR)          // elems per stage (A 128 rows + B 128)
#define MM_BOFF  (128 * MM_STR)          // B offset within stage (elems)

template<int ACT, int EMIT>
__global__ __launch_bounds__(256, 2) void mma_gemm(
    const u16* __restrict__ Ahi, const u16* __restrict__ Alo, int Kp,
    const u16* __restrict__ Bhi, const u16* __restrict__ Blo,
    const float* __restrict__ bias, int N,
    float* __restrict__ Cf, u16* __restrict__ Chi, u16* __restrict__ Clo,
    int CKp)
{
    __shared__ u16 sm[2][MM_STAGE];

    const int tid  = threadIdx.x;
    const int row0 = blockIdx.x * 128;
    const int col0 = blockIdx.y * 128;
    const int perSeg = Kp >> 5;
    const int total  = 3 * perSeg;

    // loader mapping: chunks of 16B (8 elems); A and B each 512 chunks
    const int rA0 = tid >> 2,        hA0 = tid & 3;
    const int rA1 = (tid + 256) >> 2, hA1 = (tid + 256) & 3;

    float acc[4][4][4];
#pragma unroll
    for (int i = 0; i < 4; i++)
#pragma unroll
        for (int j = 0; j < 4; j++)
#pragma unroll
            for (int e = 0; e < 4; e++) acc[i][j][e] = 0.f;

    uint4 va0, va1, vb0, vb1;

    // prologue: tile 0 (seg 0, kb 0)
    va0 = *(const uint4*)(Ahi + (size_t)(row0 + rA0) * Kp + hA0 * 8);
    va1 = *(const uint4*)(Ahi + (size_t)(row0 + rA1) * Kp + hA1 * 8);
    vb0 = *(const uint4*)(Bhi + (size_t)(col0 + rA0) * Kp + hA0 * 8);
    vb1 = *(const uint4*)(Bhi + (size_t)(col0 + rA1) * Kp + hA1 * 8);
    {
        u16* s = sm[0];
        *(uint4*)(s + rA0 * MM_STR + hA0 * 8) = va0;
        *(uint4*)(s + rA1 * MM_STR + hA1 * 8) = va1;
        *(uint4*)(s + MM_BOFF + rA0 * MM_STR + hA0 * 8) = vb0;
        *(uint4*)(s + MM_BOFF + rA1 * MM_STR + hA1 * 8) = vb1;
    }
    __syncthreads();

    const int lane = tid & 31, warp = tid >> 5;
    const int wm = warp >> 2, wn = warp & 3;
    const int lr = lane & 15, h8 = (lane >> 4) * 8;
    const uint32_t sbase = smem_u32(sm);

    int p = 0;
    for (int it = 0; it < total; it++) {
        if (it + 1 < total) {
            int nit = it + 1;
            int seg = nit / perSeg;
            int kb  = (nit - seg * perSeg) * 32;
            const u16* As = (seg == 2) ? Alo : Ahi;
            const u16* Bs = (seg == 1) ? Blo : Bhi;
            va0 = *(const uint4*)(As + (size_t)(row0 + rA0) * Kp + kb + hA0 * 8);
            va1 = *(const uint4*)(As + (size_t)(row0 + rA1) * Kp + kb + hA1 * 8);
            vb0 = *(const uint4*)(Bs + (size_t)(col0 + rA0) * Kp + kb + hA0 * 8);
            vb1 = *(const uint4*)(Bs + (size_t)(col0 + rA1) * Kp + kb + hA1 * 8);
        }

        // compute on stage p
        const uint32_t Ab = sbase + (uint32_t)p * (MM_STAGE * 2);
        const uint32_t Bb = Ab + MM_BOFF * 2;
#pragma unroll
        for (int kk = 0; kk < 2; kk++) {
            uint32_t b[2][4];
#pragma unroll
            for (int nt = 0; nt < 2; nt++)
                ldm_x4(b[nt][0], b[nt][1], b[nt][2], b[nt][3],
                       Bb + (uint32_t)(((wn * 32 + nt * 16 + lr) * MM_STR
                                        + kk * 16 + h8) * 2));
#pragma unroll
            for (int mi = 0; mi < 4; mi++) {
                uint32_t a0, a1, a2, a3;
                ldm_x4(a0, a1, a2, a3,
                       Ab + (uint32_t)(((wm * 64 + mi * 16 + lr) * MM_STR
                                        + kk * 16 + h8) * 2));
#pragma unroll
                for (int nt = 0; nt < 2; nt++) {
                    mma_bf16(acc[mi][2 * nt],     a0, a1, a2, a3, b[nt][0], b[nt][2]);
                    mma_bf16(acc[mi][2 * nt + 1], a0, a1, a2, a3, b[nt][1], b[nt][3]);
                }
            }
        }

        if (it + 1 < total) {
            u16* s = sm[p ^ 1];
            *(uint4*)(s + rA0 * MM_STR + hA0 * 8) = va0;
            *(uint4*)(s + rA1 * MM_STR + hA1 * 8) = va1;
            *(uint4*)(s + MM_BOFF + rA0 * MM_STR + hA0 * 8) = vb0;
            *(uint4*)(s + MM_BOFF + rA1 * MM_STR + hA1 * 8) = vb1;
            __syncthreads();
        }
        p ^= 1;
    }

    // Epilogue. acc[mi][ni]: columns (ni>>1)*16 + (ni&1)*8
    const int g = lane >> 2, tig = lane & 3;
#pragma unroll
    for (int mi = 0; mi < 4; mi++) {
#pragma unroll
        for (int ni = 0; ni < 4; ni++) {
            int gcol = col0 + wn * 32 + (ni >> 1) * 16 + (ni & 1) * 8 + tig * 2;
            int gr0  = row0 + wm * 64 + mi * 16 + g;
            float c0 = acc[mi][ni][0], c1 = acc[mi][ni][1];
            float c2 = acc[mi][ni][2], c3 = acc[mi][ni][3];
            if (EMIT) {
                if (gcol < CKp) {
                    float v0 = 0.f, v1 = 0.f, v2 = 0.f, v3 = 0.f;
                    if (gcol < N) {
                        float bv = bias[gcol];
                        v0 = c0 + bv; v2 = c2 + bv;
                        if (ACT) { v0 = elu_f(v0); v2 = elu_f(v2); }
                    }
                    if (gcol + 1 < N) {
                        float bv = bias[gcol + 1];
                        v1 = c1 + bv; v3 = c3 + bv;
                        if (ACT) { v1 = elu_f(v1); v3 = elu_f(v3); }
                    }
                    u16 h0, l0, h1, l1;
                    split_bf(v0, h0, l0); split_bf(v1, h1, l1);
                    size_t o = (size_t)gr0 * CKp + gcol;
                    Chi[o] = h0; Chi[o + 1] = h1;
                    Clo[o] = l0; Clo[o + 1] = l1;
                    split_bf(v2, h0, l0); split_bf(v3, h1, l1);
                    o = (size_t)(gr0 + 8) * CKp + gcol;
                    Chi[o] = h0; Chi[o + 1] = h1;
                    Clo[o] = l0; Clo[o + 1] = l1;
                }
            } else {
                if (gcol < N) {   // N even -> gcol+1 < N too
                    float b0v = bias[gcol], b1v = bias[gcol + 1];
                    float v0 = c0 + b0v, v1 = c1 + b1v;
                    float v2 = c2 + b0v, v3 = c3 + b1v;
                    if (ACT) { v0 = elu_f(v0); v1 = elu_f(v1);
                               v2 = elu_f(v2); v3 = elu_f(v3); }
                    *(float2*)(Cf + (size_t)gr0 * N + gcol)       = make_float2(v0, v1);
                    *(float2*)(Cf + (size_t)(gr0 + 8) * N + gcol) = make_float2(v2, v3);
                }
            }
        }
    }
}

// ---------------------------------------------------------------------------
// Recurrent scan v2 (R13) + bf16 hi/lo emission of states.
// ---------------------------------------------------------------------------
#define SC_C   8
#define SC_R   16
#define SC_MC  25
#define SC_BC  32
#define SC_ROWS  75
#define SC_ROWSP 80
#define SC_HSTR  202
#define SC_GSTR  34
#define SC_THREADS 256
#define SC_SMEM_FLOATS (SC_ROWSP*200 + SC_BC*SC_HSTR + SC_ROWSP*SC_GSTR + G3)

__global__ void init_flags_kernel() { g_flags[threadIdx.x] = 0u; }

__global__ __launch_bounds__(SC_THREADS) void scan_kernel(
    const float* __restrict__ GX, const float* __restrict__ Whh,
    const float* __restrict__ bhh, const float* __restrict__ in_state,
    const unsigned char* __restrict__ reset, float* __restrict__ states)
{
    extern __shared__ float sm[];
    float* sW  = sm;
    float* sH  = sW + SC_ROWSP * 200;
    float* sGH = sH + SC_BC * SC_HSTR;
    float* sBH = sGH + SC_ROWSP * SC_GSTR;

    const int c   = blockIdx.x & 7;
    const int r   = blockIdx.x >> 3;
    const int tid = threadIdx.x;
    const int rg  = tid >> 4;
    const int bg  = tid & 15;

    for (int idx = tid; idx < SC_ROWSP * 200; idx += SC_THREADS) {
        int lr = idx / 200, k = idx % 200;
        float v = 0.f;
        if (lr < SC_ROWS) {
            int g = lr / SC_MC, j = lr % SC_MC;
            int grow = g * 200 + c * SC_MC + j;
            v = Whh[(size_t)grow * 200 + k];
        }
        sW[idx] = v;
    }
    for (int idx = tid; idx < G3; idx += SC_THREADS) sBH[idx] = bhh[idx];

    float pxr[4], pxz[4], pxn[4];
#pragma unroll
    for (int q = 0; q < 4; q++) {
        int idx = tid + q * SC_THREADS;
        if (idx < SC_MC * SC_BC) {
            int bl = idx / SC_MC, j = idx % SC_MC;
            int b = r * SC_BC + bl;
            int m = c * SC_MC + j;
            size_t gxi = (size_t)b * G3 + m;
            pxr[q] = GX[gxi];
            pxz[q] = GX[gxi + 200];
            pxn[q] = GX[gxi + 400];
        } else { pxr[q] = pxz[q] = pxn[q] = 0.f; }
    }

    for (int t = 0; t < T_STEPS; t++) {
        const float* hsrc = (t == 0) ? in_state
                                     : (states + (size_t)(t - 1) * B_DIM * M_DIM);
        for (int idx = tid; idx < SC_BC * 100; idx += SC_THREADS) {
            int bl = idx / 100, kp = idx % 100;
            int b = r * SC_BC + bl;
            ull v = *(const ull*)(hsrc + (size_t)b * 200 + kp * 2);
            if (reset[t * B_DIM + b]) v = 0ull;
            *(ull*)(sH + bl * SC_HSTR + kp * 2) = v;
        }
        __syncthreads();

        ull acc[5][2];
#pragma unroll
        for (int i = 0; i < 5; i++) { acc[i][0] = 0ull; acc[i][1] = 0ull; }

        const float* hb0 = sH + (bg * 2) * SC_HSTR;
        const float* hb1 = hb0 + SC_HSTR;
#pragma unroll 2
        for (int k = 0; k < 200; k += 4) {
            ull w0[5], w1[5];
#pragma unroll
            for (int i = 0; i < 5; i++) {
                const ull* wp = (const ull*)(sW + (rg * 5 + i) * 200 + k);
                w0[i] = wp[0]; w1[i] = wp[1];
            }
            ull h00 = *(const ull*)(hb0 + k);
            ull h01 = *(const ull*)(hb0 + k + 2);
            ull h10 = *(const ull*)(hb1 + k);
            ull h11 = *(const ull*)(hb1 + k + 2);
#pragma unroll
            for (int i = 0; i < 5; i++) {
                fma2(acc[i][0], w0[i], h00);
                fma2(acc[i][0], w1[i], h01);
                fma2(acc[i][1], w0[i], h10);
                fma2(acc[i][1], w1[i], h11);
            }
        }
#pragma unroll
        for (int i = 0; i < 5; i++) {
            float l0, h0, l1, h1;
            unpack2(acc[i][0], l0, h0);
            unpack2(acc[i][1], l1, h1);
            *(ull*)(sGH + (rg * 5 + i) * SC_GSTR + bg * 2) =
                pack2(l0 + h0, l1 + h1);
        }
        __syncthreads();

#pragma unroll
        for (int q = 0; q < 4; q++) {
            int idx = tid + q * SC_THREADS;
            if (idx < SC_MC * SC_BC) {
                int bl = idx / SC_MC, j = idx % SC_MC;
                int b = r * SC_BC + bl;
                int m = c * SC_MC + j;
                float hr = sGH[j * SC_GSTR + bl]               + sBH[m];
                float hz = sGH[(SC_MC + j) * SC_GSTR + bl]     + sBH[200 + m];
                float hn = sGH[(2 * SC_MC + j) * SC_GSTR + bl] + sBH[400 + m];
                float rgate = sigm_f(pxr[q] + hr);
                float z     = sigm_f(pxz[q] + hz);
                float n     = tanhf(pxn[q] + rgate * hn);
                float hp    = sH[bl * SC_HSTR + m];
                float hnew  = (1.f - z) * n + z * hp;
                size_t grow = (size_t)(t * B_DIM) + b;
                states[(size_t)t * B_DIM * M_DIM + (size_t)b * M_DIM + m] = hnew;
                u16 hh, ll; split_bf(hnew, hh, ll);
                g_Shi[grow * KP_X + m] = hh;
                g_Slo[grow * KP_X + m] = ll;
            }
        }
        // pad cols 200..223 of Shi/Slo (owned by c==7 blocks)
        if (c == 7) {
            for (int idx = tid; idx < SC_BC * 24; idx += SC_THREADS) {
                int bl = idx / 24, mm = 200 + idx % 24;
                size_t grow = (size_t)(t * B_DIM) + r * SC_BC + bl;
                g_Shi[grow * KP_X + mm] = 0;
                g_Slo[grow * KP_X + mm] = 0;
            }
        }

        if (t + 1 < T_STEPS) {
            __syncthreads();
            if (tid == 0) {
                asm volatile("st.release.gpu.global.u32 [%0], %1;"
                             :: "l"(g_flags + blockIdx.x), "r"((unsigned)(t + 1))
                             : "memory");
            }
            size_t gbase = (size_t)((t + 1) * B_DIM) * G3;
#pragma unroll
            for (int q = 0; q < 4; q++) {
                int idx = tid + q * SC_THREADS;
                if (idx < SC_MC * SC_BC) {
                    int bl = idx / SC_MC, j = idx % SC_MC;
                    int b = r * SC_BC + bl;
                    int m = c * SC_MC + j;
                    size_t gxi = gbase + (size_t)b * G3 + m;
                    pxr[q] = GX[gxi];
                    pxz[q] = GX[gxi + 200];
                    pxn[q] = GX[gxi + 400];
                }
            }
            if (tid < SC_C) {
                const unsigned int* fp = g_flags + (r << 3) + tid;
                unsigned int v;
                do {
                    asm volatile("ld.acquire.gpu.global.u32 %0, [%1];"
                                 : "=r"(v) : "l"(fp) : "memory");
                } while (v < (unsigned)(t + 1));
            }
            __syncthreads();
        }
    }
}

// ---------------------------------------------------------------------------
// Sample head (unchanged): partitionable threefry, bits = o0^o1.
// ---------------------------------------------------------------------------
__global__ void sample_kernel(const float* __restrict__ posts_last,
                              float* __restrict__ out)
{
    int i = blockIdx.x * blockDim.x + threadIdx.x;
    const int NTOT = B_DIM * S_DIM;
    if (i >= NTOT) return;

    uint32_t x0 = 0u, x1 = (uint32_t)i;
    const uint32_t ks0 = 0u, ks1 = 42u, ks2 = 0u ^ 42u ^ 0x1BD11BDAu;
    x0 += ks0; x1 += ks1;
#define TF_RND(rot) { x0 += x1; x1 = (x1 << (rot)) | (x1 >> (32 - (rot))); x1 ^= x0; }
    TF_RND(13) TF_RND(15) TF_RND(26) TF_RND(6)   x0 += ks1; x1 += ks2 + 1u;
    TF_RND(17) TF_RND(29) TF_RND(16) TF_RND(24)  x0 += ks2; x1 += ks0 + 2u;
    TF_RND(13) TF_RND(15) TF_RND(26) TF_RND(6)   x0 += ks0; x1 += ks1 + 3u;
    TF_RND(17) TF_RND(29) TF_RND(16) TF_RND(24)  x0 += ks1; x1 += ks2 + 4u;
    TF_RND(13) TF_RND(15) TF_RND(26) TF_RND(6)   x0 += ks2; x1 += ks0 + 5u;
#undef TF_RND
    uint32_t bits = x0 ^ x1;

    float f = __uint_as_float((bits >> 9) | 0x3F800000u) - 1.0f;
    const float lo = -0.99999994f;
    float u = fmaxf(lo, f * 2.0f + lo);
    float noise = 1.41421356f * erfinvf(u);

    int b = i / S_DIM, s = i % S_DIM;
    float mean = posts_last[(size_t)b * 60 + s];
    float sraw = posts_last[(size_t)b * 60 + 30 + s];
    float stdv = fmaxf(sraw, 0.f) + log1pf(expf(-fabsf(sraw))) + 0.1f;
    out[i] = mean + stdv * noise;
}

// ---------------------------------------------------------------------------
extern "C" void kernel_launch(void* const* d_in, const int* in_sizes, int n_in,
                              void* d_out, int out_size)
{
    const float* embed    = (const float*)d_in[0];
    const float* action   = (const float*)d_in[1];
    const unsigned char* reset = (const unsigned char*)d_in[2];
    const float* in_state = (const float*)d_in[3];
    const float* W1 = (const float*)d_in[4];
    const float* b1 = (const float*)d_in[5];
    const float *Wih, *bih, *Whh, *bhh;
    if (in_sizes[7] == 600) {          // dict order: Wih, bih, Whh, bhh
        Wih = (const float*)d_in[6]; bih = (const float*)d_in[7];
        Whh = (const float*)d_in[8]; bhh = (const float*)d_in[9];
    } else {                           // signature order: Wih, Whh, bih, bhh
        Wih = (const float*)d_in[6]; Whh = (const float*)d_in[7];
        bih = (const float*)d_in[8]; bhh = (const float*)d_in[9];
    }
    const float* W2 = (const float*)d_in[10];
    const float* b2 = (const float*)d_in[11];
    const float* W3 = (const float*)d_in[12];
    const float* b3 = (const float*)d_in[13];

    float* out    = (float*)d_out;
    float* sample = out;                                  // [512,30]
    float* states = out + (size_t)B_DIM * S_DIM;          // [256,512,200]
    float* posts  = states + (size_t)T_STEPS * B_DIM * M_DIM; // [256,512,60]

    float* GXbuf; cudaGetSymbolAddress((void**)&GXbuf, g_GX);
    u16 *EAh, *EAl, *Xh, *Xl, *Sh, *Sl;
    u16 *W1h, *W1l, *Wihh, *Wihl, *W2h, *W2l, *W3h, *W3l;
    cudaGetSymbolAddress((void**)&EAh, g_EAhi);
    cudaGetSymbolAddress((void**)&EAl, g_EAlo);
    cudaGetSymbolAddress((void**)&Xh, g_Xhi);
    cudaGetSymbolAddress((void**)&Xl, g_Xlo);
    cudaGetSymbolAddress((void**)&Sh, g_Shi);
    cudaGetSymbolAddress((void**)&Sl, g_Slo);
    cudaGetSymbolAddress((void**)&W1h, g_W1h);
    cudaGetSymbolAddress((void**)&W1l, g_W1l);
    cudaGetSymbolAddress((void**)&Wihh, g_Wih_h);
    cudaGetSymbolAddress((void**)&Wihl, g_Wih_l);
    cudaGetSymbolAddress((void**)&W2h, g_W2h);
    cudaGetSymbolAddress((void**)&W2l, g_W2l);
    cudaGetSymbolAddress((void**)&W3h, g_W3h);
    cudaGetSymbolAddress((void**)&W3l, g_W3l);

    // Converters (once per operand)
    {
        size_t n = (size_t)TB * KP_EA;
        cvt_ea_kernel<<<(unsigned)((n + 255) / 256), 256>>>(embed, action);
    }
    cvt_w_kernel<<<(256 * KP_EA + 255) / 256, 256>>>(W1, H_DIM, EA_DIM, KP_EA, 256, W1h, W1l);
    cvt_w_kernel<<<(640 * KP_X + 255) / 256, 256>>>(Wih, G3, H_DIM, KP_X, 640, Wihh, Wihl);
    cvt_w_kernel<<<(256 * KP_X + 255) / 256, 256>>>(W2, H_DIM, M_DIM, KP_X, 256, W2h, W2l);
    cvt_w_kernel<<<(128 * KP_X + 255) / 256, 256>>>(W3, 2 * S_DIM, H_DIM, KP_X, 128, W3h, W3l);

    // K1: X = elu(EA @ W1^T + b1) -> bf16 hi/lo (stride 224)
    mma_gemm<1, 1><<<dim3(TB / 128, 2), 256>>>(
        EAh, EAl, KP_EA, W1h, W1l, b1, H_DIM, nullptr, Xh, Xl, KP_X);

    // K2: GX = X @ Wih^T + bih -> fp32
    mma_gemm<0, 0><<<dim3(TB / 128, 5), 256>>>(
        Xh, Xl, KP_X, Wihh, Wihl, bih, G3, GXbuf, nullptr, nullptr, 0);

    // K3: recurrent scan -> states (fp32) + Shi/Slo (bf16)
    init_flags_kernel<<<1, 128>>>();
    cudaFuncSetAttribute(scan_kernel,
                         cudaFuncAttributeMaxDynamicSharedMemorySize,
                         SC_SMEM_FLOATS * (int)sizeof(float));
    scan_kernel<<<SC_C * SC_R, SC_THREADS, SC_SMEM_FLOATS * sizeof(float)>>>(
        GXbuf, Whh, bhh, in_state, reset, states);

    // K4: P1 = elu(S @ W2^T + b2) -> bf16 hi/lo (reuse EA buffers, stride 224)
    mma_gemm<1, 1><<<dim3(TB / 128, 2), 256>>>(
        Sh, Sl, KP_X, W2h, W2l, b2, H_DIM, nullptr, EAh, EAl, KP_X);

    // K5: posts = P1 @ W3^T + b3 -> fp32
    mma_gemm<0, 0><<<dim3(TB / 128, 1), 256>>>(
        EAh, EAl, KP_X, W3h, W3l, b3, 2 * S_DIM, posts, nullptr, nullptr, 0);

    // K6: sample
    const float* posts_last = posts + (size_t)(T_STEPS - 1) * B_DIM * 2 * S_DIM;
    sample_kernel<<<(B_DIM * S_DIM + 255) / 256, 256>>>(posts_last, sample);
}

// round 17
// speedup vs baseline: 1.0969x; 1.0167x over previous
#include <cuda_runtime.h>
#include <cuda_bf16.h>
#include <cstdint>
#include <cstddef>

// Problem dims
#define T_STEPS 256
#define B_DIM   512
#define E_DIM   256
#define A_DIM   7
#define M_DIM   200
#define S_DIM   30
#define H_DIM   200
#define EA_DIM  263
#define G3      600
#define TB      131072   // T*B

typedef unsigned long long ull;
typedef unsigned short u16;

// bf16 operand buffers (hi/lo split), padded K dims: EA->288, X/S/P1->224
#define KP_EA 288
#define KP_X  224

__device__ float g_GX[(size_t)TB * 600];
__device__ unsigned int g_flags[128];

__device__ u16 g_EAhi[(size_t)TB * KP_EA];
__device__ u16 g_EAlo[(size_t)TB * KP_EA];   // later reused for P1 (stride 224)
__device__ u16 g_Xhi[(size_t)TB * KP_X];
__device__ u16 g_Xlo[(size_t)TB * KP_X];
__device__ u16 g_Shi[(size_t)TB * KP_X];
__device__ u16 g_Slo[(size_t)TB * KP_X];
// weights (rows padded to multiple of 128)
__device__ u16 g_W1h[256 * KP_EA], g_W1l[256 * KP_EA];
__device__ u16 g_Wih_h[640 * KP_X], g_Wih_l[640 * KP_X];
__device__ u16 g_W2h[256 * KP_X], g_W2l[256 * KP_X];
__device__ u16 g_W3h[128 * KP_X], g_W3l[128 * KP_X];

__device__ __forceinline__ float elu_f(float x) { return x > 0.f ? x : expm1f(x); }
__device__ __forceinline__ float sigm_f(float x) { return 1.f / (1.f + expf(-x)); }

__device__ __forceinline__ void split_bf(float f, u16& h, u16& l) {
    __nv_bfloat16 hb = __float2bfloat16_rn(f);
    float r = f - __bfloat162float(hb);
    h = __bfloat16_as_ushort(hb);
    l = __bfloat16_as_ushort(__float2bfloat16_rn(r));
}

// Packed f32x2 helpers (scan only)
__device__ __forceinline__ void fma2(ull& d, ull a, ull b) {
    asm("fma.rn.f32x2 %0, %1, %2, %3;" : "=l"(d) : "l"(a), "l"(b), "l"(d));
}
__device__ __forceinline__ ull pack2(float x, float y) {
    ull r;
    asm("mov.b64 %0, {%1, %2};" : "=l"(r)
        : "r"(__float_as_uint(x)), "r"(__float_as_uint(y)));
    return r;
}
__device__ __forceinline__ void unpack2(ull v, float& lo, float& hi) {
    unsigned int a, b;
    asm("mov.b64 {%0, %1}, %2;" : "=r"(a), "=r"(b) : "l"(v));
    lo = __uint_as_float(a); hi = __uint_as_float(b);
}

__device__ __forceinline__ uint32_t smem_u32(const void* p) {
    uint32_t a;
    asm("{ .reg .u64 t; cvta.to.shared.u64 t, %1; cvt.u32.u64 %0, t; }"
        : "=r"(a) : "l"(p));
    return a;
}
__device__ __forceinline__ void ldm_x4(uint32_t& r0, uint32_t& r1,
                                       uint32_t& r2, uint32_t& r3, uint32_t addr) {
    asm volatile("ldmatrix.sync.aligned.m8n8.x4.shared.b16 {%0,%1,%2,%3}, [%4];"
                 : "=r"(r0), "=r"(r1), "=r"(r2), "=r"(r3) : "r"(addr));
}
__device__ __forceinline__ void mma_bf16(float* c,
                                         uint32_t a0, uint32_t a1, uint32_t a2, uint32_t a3,
                                         uint32_t b0, uint32_t b1) {
    asm volatile("mma.sync.aligned.m16n8k16.row.col.f32.bf16.bf16.f32 "
                 "{%0,%1,%2,%3},{%4,%5,%6,%7},{%8,%9},{%0,%1,%2,%3};"
                 : "+f"(c[0]), "+f"(c[1]), "+f"(c[2]), "+f"(c[3])
                 : "r"(a0), "r"(a1), "r"(a2), "r"(a3), "r"(b0), "r"(b1));
}

// cp.async (sm_80 PTX -> LDGSTS; legal on plain sm_103)
__device__ __forceinline__ void cp_async16(uint32_t saddr, const void* gaddr) {
    asm volatile("cp.async.ca.shared.global [%0], [%1], 16;"
                 :: "r"(saddr), "l"(gaddr) : "memory");
}
#define CP_COMMIT() asm volatile("cp.async.commit_group;" ::: "memory")
#define CP_WAIT(n)  asm volatile("cp.async.wait_group %0;" :: "n"(n) : "memory")

// ---------------------------------------------------------------------------
// Converters (run once per operand)
// ---------------------------------------------------------------------------
__global__ void cvt_ea_kernel(const float* __restrict__ embed,
                              const float* __restrict__ action)
{
    size_t idx = (size_t)blockIdx.x * blockDim.x + threadIdx.x;
    if (idx >= (size_t)TB * KP_EA) return;
    int row = (int)(idx / KP_EA), col = (int)(idx % KP_EA);
    float f = 0.f;
    if (col < E_DIM)        f = embed[(size_t)row * E_DIM + col];
    else if (col < EA_DIM)  f = action[(size_t)row * A_DIM + (col - E_DIM)];
    u16 h, l; split_bf(f, h, l);
    g_EAhi[idx] = h; g_EAlo[idx] = l;
}

__global__ void cvt_w_kernel(const float* __restrict__ W, int N, int K,
                             int Kp, int Np, u16* __restrict__ Wh,
                             u16* __restrict__ Wl)
{
    int idx = blockIdx.x * blockDim.x + threadIdx.x;
    if (idx >= Np * Kp) return;
    int r = idx / Kp, k = idx % Kp;
    float f = (r < N && k < K) ? W[(size_t)r * K + k] : 0.f;
    u16 h, l; split_bf(f, h, l);
    Wh[idx] = h; Wl[idx] = l;
}

// ---------------------------------------------------------------------------
// Pipelined BF16 mma GEMM, cp.async staging (2-stage):
//   C = Ahi*Bhi + Ahi*Blo + Alo*Bhi   over K' = 3*Kp (segment select per tile)
// Block 128x128, BK=32, 256 threads = 8 warps (2M x 4N), warp tile 64x32.
// smem stride 40 elems (80B), conflict-free ldmatrix.
// ---------------------------------------------------------------------------
#define MM_STR 40
#define MM_STAGE (256 * MM_STR)          // elems per stage (A 128 rows + B 128)
#define MM_BOFF  (128 * MM_STR)          // B offset within stage (elems)

template<int ACT, int EMIT>
__global__ __launch_bounds__(256, 2) void mma_gemm(
    const u16* __restrict__ Ahi, const u16* __restrict__ Alo, int Kp,
    const u16* __restrict__ Bhi, const u16* __restrict__ Blo,
    const float* __restrict__ bias, int N,
    float* __restrict__ Cf, u16* __restrict__ Chi, u16* __restrict__ Clo,
    int CKp)
{
    __shared__ u16 sm[2][MM_STAGE];

    const int tid  = threadIdx.x;
    const int row0 = blockIdx.x * 128;
    const int col0 = blockIdx.y * 128;
    const int perSeg = Kp >> 5;
    const int total  = 3 * perSeg;

    // loader mapping: chunks of 16B (8 elems); A and B each 512 chunks
    const int rA0 = tid >> 2,         hA0 = tid & 3;
    const int rA1 = (tid + 256) >> 2, hA1 = (tid + 256) & 3;

    // smem destinations (stage 0); stage 1 adds MM_STAGE*2 bytes
    const uint32_t sA0 = smem_u32(sm[0] + rA0 * MM_STR + hA0 * 8);
    const uint32_t sA1 = smem_u32(sm[0] + rA1 * MM_STR + hA1 * 8);
    const uint32_t sB0 = smem_u32(sm[0] + MM_BOFF + rA0 * MM_STR + hA0 * 8);
    const uint32_t sB1 = smem_u32(sm[0] + MM_BOFF + rA1 * MM_STR + hA1 * 8);

    float acc[4][4][4];
#pragma unroll
    for (int i = 0; i < 4; i++)
#pragma unroll
        for (int j = 0; j < 4; j++)
#pragma unroll
            for (int e = 0; e < 4; e++) acc[i][j][e] = 0.f;

    // prologue: stage 0 (seg 0, kb 0)
    cp_async16(sA0, Ahi + (size_t)(row0 + rA0) * Kp + hA0 * 8);
    cp_async16(sA1, Ahi + (size_t)(row0 + rA1) * Kp + hA1 * 8);
    cp_async16(sB0, Bhi + (size_t)(col0 + rA0) * Kp + hA0 * 8);
    cp_async16(sB1, Bhi + (size_t)(col0 + rA1) * Kp + hA1 * 8);
    CP_COMMIT();

    const int lane = tid & 31, warp = tid >> 5;
    const int wm = warp >> 2, wn = warp & 3;
    const int lr = lane & 15, h8 = (lane >> 4) * 8;
    const uint32_t sbase = smem_u32(sm);

    int p = 0;
    for (int it = 0; it < total; it++) {
        if (it + 1 < total) {
            int nit = it + 1;
            int seg = nit / perSeg;
            int kb  = (nit - seg * perSeg) * 32;
            const u16* As = (seg == 2) ? Alo : Ahi;
            const u16* Bs = (seg == 1) ? Blo : Bhi;
            const uint32_t soff = (uint32_t)((p ^ 1) * (MM_STAGE * 2));
            cp_async16(sA0 + soff, As + (size_t)(row0 + rA0) * Kp + kb + hA0 * 8);
            cp_async16(sA1 + soff, As + (size_t)(row0 + rA1) * Kp + kb + hA1 * 8);
            cp_async16(sB0 + soff, Bs + (size_t)(col0 + rA0) * Kp + kb + hA0 * 8);
            cp_async16(sB1 + soff, Bs + (size_t)(col0 + rA1) * Kp + kb + hA1 * 8);
            CP_COMMIT();
            CP_WAIT(1);          // stage p complete; stage p^1 in flight
        } else {
            CP_WAIT(0);
        }
        __syncthreads();

        // compute on stage p
        const uint32_t Ab = sbase + (uint32_t)p * (MM_STAGE * 2);
        const uint32_t Bb = Ab + MM_BOFF * 2;
#pragma unroll
        for (int kk = 0; kk < 2; kk++) {
            uint32_t b[2][4];
#pragma unroll
            for (int nt = 0; nt < 2; nt++)
                ldm_x4(b[nt][0], b[nt][1], b[nt][2], b[nt][3],
                       Bb + (uint32_t)(((wn * 32 + nt * 16 + lr) * MM_STR
                                        + kk * 16 + h8) * 2));
#pragma unroll
            for (int mi = 0; mi < 4; mi++) {
                uint32_t a0, a1, a2, a3;
                ldm_x4(a0, a1, a2, a3,
                       Ab + (uint32_t)(((wm * 64 + mi * 16 + lr) * MM_STR
                                        + kk * 16 + h8) * 2));
#pragma unroll
                for (int nt = 0; nt < 2; nt++) {
                    mma_bf16(acc[mi][2 * nt],     a0, a1, a2, a3, b[nt][0], b[nt][2]);
                    mma_bf16(acc[mi][2 * nt + 1], a0, a1, a2, a3, b[nt][1], b[nt][3]);
                }
            }
        }
        __syncthreads();   // compute done before stage p is overwritten next it
        p ^= 1;
    }

    // Epilogue. acc[mi][ni]: columns (ni>>1)*16 + (ni&1)*8
    const int g = lane >> 2, tig = lane & 3;
#pragma unroll
    for (int mi = 0; mi < 4; mi++) {
#pragma unroll
        for (int ni = 0; ni < 4; ni++) {
            int gcol = col0 + wn * 32 + (ni >> 1) * 16 + (ni & 1) * 8 + tig * 2;
            int gr0  = row0 + wm * 64 + mi * 16 + g;
            float c0 = acc[mi][ni][0], c1 = acc[mi][ni][1];
            float c2 = acc[mi][ni][2], c3 = acc[mi][ni][3];
            if (EMIT) {
                if (gcol < CKp) {
                    float v0 = 0.f, v1 = 0.f, v2 = 0.f, v3 = 0.f;
                    if (gcol < N) {
                        float bv = bias[gcol];
                        v0 = c0 + bv; v2 = c2 + bv;
                        if (ACT) { v0 = elu_f(v0); v2 = elu_f(v2); }
                    }
                    if (gcol + 1 < N) {
                        float bv = bias[gcol + 1];
                        v1 = c1 + bv; v3 = c3 + bv;
                        if (ACT) { v1 = elu_f(v1); v3 = elu_f(v3); }
                    }
                    u16 h0, l0, h1, l1;
                    split_bf(v0, h0, l0); split_bf(v1, h1, l1);
                    size_t o = (size_t)gr0 * CKp + gcol;
                    Chi[o] = h0; Chi[o + 1] = h1;
                    Clo[o] = l0; Clo[o + 1] = l1;
                    split_bf(v2, h0, l0); split_bf(v3, h1, l1);
                    o = (size_t)(gr0 + 8) * CKp + gcol;
                    Chi[o] = h0; Chi[o + 1] = h1;
                    Clo[o] = l0; Clo[o + 1] = l1;
                }
            } else {
                if (gcol < N) {   // N even -> gcol+1 < N too
                    float b0v = bias[gcol], b1v = bias[gcol + 1];
                    float v0 = c0 + b0v, v1 = c1 + b1v;
                    float v2 = c2 + b0v, v3 = c3 + b1v;
                    if (ACT) { v0 = elu_f(v0); v1 = elu_f(v1);
                               v2 = elu_f(v2); v3 = elu_f(v3); }
                    *(float2*)(Cf + (size_t)gr0 * N + gcol)       = make_float2(v0, v1);
                    *(float2*)(Cf + (size_t)(gr0 + 8) * N + gcol) = make_float2(v2, v3);
                }
            }
        }
    }
}

// ---------------------------------------------------------------------------
// Recurrent scan v2 (R13) + bf16 hi/lo emission of states.
// ---------------------------------------------------------------------------
#define SC_C   8
#define SC_R   16
#define SC_MC  25
#define SC_BC  32
#define SC_ROWS  75
#define SC_ROWSP 80
#define SC_HSTR  202
#define SC_GSTR  34
#define SC_THREADS 256
#define SC_SMEM_FLOATS (SC_ROWSP*200 + SC_BC*SC_HSTR + SC_ROWSP*SC_GSTR + G3)

__global__ void init_flags_kernel() { g_flags[threadIdx.x] = 0u; }

__global__ __launch_bounds__(SC_THREADS) void scan_kernel(
    const float* __restrict__ GX, const float* __restrict__ Whh,
    const float* __restrict__ bhh, const float* __restrict__ in_state,
    const unsigned char* __restrict__ reset, float* __restrict__ states)
{
    extern __shared__ float sm[];
    float* sW  = sm;
    float* sH  = sW + SC_ROWSP * 200;
    float* sGH = sH + SC_BC * SC_HSTR;
    float* sBH = sGH + SC_ROWSP * SC_GSTR;

    const int c   = blockIdx.x & 7;
    const int r   = blockIdx.x >> 3;
    const int tid = threadIdx.x;
    const int rg  = tid >> 4;
    const int bg  = tid & 15;

    for (int idx = tid; idx < SC_ROWSP * 200; idx += SC_THREADS) {
        int lr = idx / 200, k = idx % 200;
        float v = 0.f;
        if (lr < SC_ROWS) {
            int g = lr / SC_MC, j = lr % SC_MC;
            int grow = g * 200 + c * SC_MC + j;
            v = Whh[(size_t)grow * 200 + k];
        }
        sW[idx] = v;
    }
    for (int idx = tid; idx < G3; idx += SC_THREADS) sBH[idx] = bhh[idx];

    float pxr[4], pxz[4], pxn[4];
#pragma unroll
    for (int q = 0; q < 4; q++) {
        int idx = tid + q * SC_THREADS;
        if (idx < SC_MC * SC_BC) {
            int bl = idx / SC_MC, j = idx % SC_MC;
            int b = r * SC_BC + bl;
            int m = c * SC_MC + j;
            size_t gxi = (size_t)b * G3 + m;
            pxr[q] = GX[gxi];
            pxz[q] = GX[gxi + 200];
            pxn[q] = GX[gxi + 400];
        } else { pxr[q] = pxz[q] = pxn[q] = 0.f; }
    }

    for (int t = 0; t < T_STEPS; t++) {
        const float* hsrc = (t == 0) ? in_state
                                     : (states + (size_t)(t - 1) * B_DIM * M_DIM);
        for (int idx = tid; idx < SC_BC * 100; idx += SC_THREADS) {
            int bl = idx / 100, kp = idx % 100;
            int b = r * SC_BC + bl;
            ull v = *(const ull*)(hsrc + (size_t)b * 200 + kp * 2);
            if (reset[t * B_DIM + b]) v = 0ull;
            *(ull*)(sH + bl * SC_HSTR + kp * 2) = v;
        }
        __syncthreads();

        ull acc[5][2];
#pragma unroll
        for (int i = 0; i < 5; i++) { acc[i][0] = 0ull; acc[i][1] = 0ull; }

        const float* hb0 = sH + (bg * 2) * SC_HSTR;
        const float* hb1 = hb0 + SC_HSTR;
#pragma unroll 2
        for (int k = 0; k < 200; k += 4) {
            ull w0[5], w1[5];
#pragma unroll
            for (int i = 0; i < 5; i++) {
                const ull* wp = (const ull*)(sW + (rg * 5 + i) * 200 + k);
                w0[i] = wp[0]; w1[i] = wp[1];
            }
            ull h00 = *(const ull*)(hb0 + k);
            ull h01 = *(const ull*)(hb0 + k + 2);
            ull h10 = *(const ull*)(hb1 + k);
            ull h11 = *(const ull*)(hb1 + k + 2);
#pragma unroll
            for (int i = 0; i < 5; i++) {
                fma2(acc[i][0], w0[i], h00);
                fma2(acc[i][0], w1[i], h01);
                fma2(acc[i][1], w0[i], h10);
                fma2(acc[i][1], w1[i], h11);
            }
        }
#pragma unroll
        for (int i = 0; i < 5; i++) {
            float l0, h0, l1, h1;
            unpack2(acc[i][0], l0, h0);
            unpack2(acc[i][1], l1, h1);
            *(ull*)(sGH + (rg * 5 + i) * SC_GSTR + bg * 2) =
                pack2(l0 + h0, l1 + h1);
        }
        __syncthreads();

#pragma unroll
        for (int q = 0; q < 4; q++) {
            int idx = tid + q * SC_THREADS;
            if (idx < SC_MC * SC_BC) {
                int bl = idx / SC_MC, j = idx % SC_MC;
                int b = r * SC_BC + bl;
                int m = c * SC_MC + j;
                float hr = sGH[j * SC_GSTR + bl]               + sBH[m];
                float hz = sGH[(SC_MC + j) * SC_GSTR + bl]     + sBH[200 + m];
                float hn = sGH[(2 * SC_MC + j) * SC_GSTR + bl] + sBH[400 + m];
                float rgate = sigm_f(pxr[q] + hr);
                float z     = sigm_f(pxz[q] + hz);
                float n     = tanhf(pxn[q] + rgate * hn);
                float hp    = sH[bl * SC_HSTR + m];
                float hnew  = (1.f - z) * n + z * hp;
                size_t grow = (size_t)(t * B_DIM) + b;
                states[(size_t)t * B_DIM * M_DIM + (size_t)b * M_DIM + m] = hnew;
                u16 hh, ll; split_bf(hnew, hh, ll);
                g_Shi[grow * KP_X + m] = hh;
                g_Slo[grow * KP_X + m] = ll;
            }
        }
        // pad cols 200..223 of Shi/Slo (owned by c==7 blocks)
        if (c == 7) {
            for (int idx = tid; idx < SC_BC * 24; idx += SC_THREADS) {
                int bl = idx / 24, mm = 200 + idx % 24;
                size_t grow = (size_t)(t * B_DIM) + r * SC_BC + bl;
                g_Shi[grow * KP_X + mm] = 0;
                g_Slo[grow * KP_X + mm] = 0;
            }
        }

        if (t + 1 < T_STEPS) {
            __syncthreads();
            if (tid == 0) {
                asm volatile("st.release.gpu.global.u32 [%0], %1;"
                             :: "l"(g_flags + blockIdx.x), "r"((unsigned)(t + 1))
                             : "memory");
            }
            size_t gbase = (size_t)((t + 1) * B_DIM) * G3;
#pragma unroll
            for (int q = 0; q < 4; q++) {
                int idx = tid + q * SC_THREADS;
                if (idx < SC_MC * SC_BC) {
                    int bl = idx / SC_MC, j = idx % SC_MC;
                    int b = r * SC_BC + bl;
                    int m = c * SC_MC + j;
                    size_t gxi = gbase + (size_t)b * G3 + m;
                    pxr[q] = GX[gxi];
                    pxz[q] = GX[gxi + 200];
                    pxn[q] = GX[gxi + 400];
                }
            }
            if (tid < SC_C) {
                const unsigned int* fp = g_flags + (r << 3) + tid;
                unsigned int v;
                do {
                    asm volatile("ld.acquire.gpu.global.u32 %0, [%1];"
                                 : "=r"(v) : "l"(fp) : "memory");
                } while (v < (unsigned)(t + 1));
            }
            __syncthreads();
        }
    }
}

// ---------------------------------------------------------------------------
// Sample head (unchanged): partitionable threefry, bits = o0^o1.
// ---------------------------------------------------------------------------
__global__ void sample_kernel(const float* __restrict__ posts_last,
                              float* __restrict__ out)
{
    int i = blockIdx.x * blockDim.x + threadIdx.x;
    const int NTOT = B_DIM * S_DIM;
    if (i >= NTOT) return;

    uint32_t x0 = 0u, x1 = (uint32_t)i;
    const uint32_t ks0 = 0u, ks1 = 42u, ks2 = 0u ^ 42u ^ 0x1BD11BDAu;
    x0 += ks0; x1 += ks1;
#define TF_RND(rot) { x0 += x1; x1 = (x1 << (rot)) | (x1 >> (32 - (rot))); x1 ^= x0; }
    TF_RND(13) TF_RND(15) TF_RND(26) TF_RND(6)   x0 += ks1; x1 += ks2 + 1u;
    TF_RND(17) TF_RND(29) TF_RND(16) TF_RND(24)  x0 += ks2; x1 += ks0 + 2u;
    TF_RND(13) TF_RND(15) TF_RND(26) TF_RND(6)   x0 += ks0; x1 += ks1 + 3u;
    TF_RND(17) TF_RND(29) TF_RND(16) TF_RND(24)  x0 += ks1; x1 += ks2 + 4u;
    TF_RND(13) TF_RND(15) TF_RND(26) TF_RND(6)   x0 += ks2; x1 += ks0 + 5u;
#undef TF_RND
    uint32_t bits = x0 ^ x1;

    float f = __uint_as_float((bits >> 9) | 0x3F800000u) - 1.0f;
    const float lo = -0.99999994f;
    float u = fmaxf(lo, f * 2.0f + lo);
    float noise = 1.41421356f * erfinvf(u);

    int b = i / S_DIM, s = i % S_DIM;
    float mean = posts_last[(size_t)b * 60 + s];
    float sraw = posts_last[(size_t)b * 60 + 30 + s];
    float stdv = fmaxf(sraw, 0.f) + log1pf(expf(-fabsf(sraw))) + 0.1f;
    out[i] = mean + stdv * noise;
}

// ---------------------------------------------------------------------------
extern "C" void kernel_launch(void* const* d_in, const int* in_sizes, int n_in,
                              void* d_out, int out_size)
{
    const float* embed    = (const float*)d_in[0];
    const float* action   = (const float*)d_in[1];
    const unsigned char* reset = (const unsigned char*)d_in[2];
    const float* in_state = (const float*)d_in[3];
    const float* W1 = (const float*)d_in[4];
    const float* b1 = (const float*)d_in[5];
    const float *Wih, *bih, *Whh, *bhh;
    if (in_sizes[7] == 600) {          // dict order: Wih, bih, Whh, bhh
        Wih = (const float*)d_in[6]; bih = (const float*)d_in[7];
        Whh = (const float*)d_in[8]; bhh = (const float*)d_in[9];
    } else {                           // signature order: Wih, Whh, bih, bhh
        Wih = (const float*)d_in[6]; Whh = (const float*)d_in[7];
        bih = (const float*)d_in[8]; bhh = (const float*)d_in[9];
    }
    const float* W2 = (const float*)d_in[10];
    const float* b2 = (const float*)d_in[11];
    const float* W3 = (const float*)d_in[12];
    const float* b3 = (const float*)d_in[13];

    float* out    = (float*)d_out;
    float* sample = out;                                  // [512,30]
    float* states = out + (size_t)B_DIM * S_DIM;          // [256,512,200]
    float* posts  = states + (size_t)T_STEPS * B_DIM * M_DIM; // [256,512,60]

    float* GXbuf; cudaGetSymbolAddress((void**)&GXbuf, g_GX);
    u16 *EAh, *EAl, *Xh, *Xl, *Sh, *Sl;
    u16 *W1h, *W1l, *Wihh, *Wihl, *W2h, *W2l, *W3h, *W3l;
    cudaGetSymbolAddress((void**)&EAh, g_EAhi);
    cudaGetSymbolAddress((void**)&EAl, g_EAlo);
    cudaGetSymbolAddress((void**)&Xh, g_Xhi);
    cudaGetSymbolAddress((void**)&Xl, g_Xlo);
    cudaGetSymbolAddress((void**)&Sh, g_Shi);
    cudaGetSymbolAddress((void**)&Sl, g_Slo);
    cudaGetSymbolAddress((void**)&W1h, g_W1h);
    cudaGetSymbolAddress((void**)&W1l, g_W1l);
    cudaGetSymbolAddress((void**)&Wihh, g_Wih_h);
    cudaGetSymbolAddress((void**)&Wihl, g_Wih_l);
    cudaGetSymbolAddress((void**)&W2h, g_W2h);
    cudaGetSymbolAddress((void**)&W2l, g_W2l);
    cudaGetSymbolAddress((void**)&W3h, g_W3h);
    cudaGetSymbolAddress((void**)&W3l, g_W3l);

    // Converters (once per operand)
    {
        size_t n = (size_t)TB * KP_EA;
        cvt_ea_kernel<<<(unsigned)((n + 255) / 256), 256>>>(embed, action);
    }
    cvt_w_kernel<<<(256 * KP_EA + 255) / 256, 256>>>(W1, H_DIM, EA_DIM, KP_EA, 256, W1h, W1l);
    cvt_w_kernel<<<(640 * KP_X + 255) / 256, 256>>>(Wih, G3, H_DIM, KP_X, 640, Wihh, Wihl);
    cvt_w_kernel<<<(256 * KP_X + 255) / 256, 256>>>(W2, H_DIM, M_DIM, KP_X, 256, W2h, W2l);
    cvt_w_kernel<<<(128 * KP_X + 255) / 256, 256>>>(W3, 2 * S_DIM, H_DIM, KP_X, 128, W3h, W3l);

    // K1: X = elu(EA @ W1^T + b1) -> bf16 hi/lo (stride 224)
    mma_gemm<1, 1><<<dim3(TB / 128, 2), 256>>>(
        EAh, EAl, KP_EA, W1h, W1l, b1, H_DIM, nullptr, Xh, Xl, KP_X);

    // K2: GX = X @ Wih^T + bih -> fp32
    mma_gemm<0, 0><<<dim3(TB / 128, 5), 256>>>(
        Xh, Xl, KP_X, Wihh, Wihl, bih, G3, GXbuf, nullptr, nullptr, 0);

    // K3: recurrent scan -> states (fp32) + Shi/Slo (bf16)
    init_flags_kernel<<<1, 128>>>();
    cudaFuncSetAttribute(scan_kernel,
                         cudaFuncAttributeMaxDynamicSharedMemorySize,
                         SC_SMEM_FLOATS * (int)sizeof(float));
    scan_kernel<<<SC_C * SC_R, SC_THREADS, SC_SMEM_FLOATS * sizeof(float)>>>(
        GXbuf, Whh, bhh, in_state, reset, states);

    // K4: P1 = elu(S @ W2^T + b2) -> bf16 hi/lo (reuse EA buffers, stride 224)
    mma_gemm<1, 1><<<dim3(TB / 128, 2), 256>>>(
        Sh, Sl, KP_X, W2h, W2l, b2, H_DIM, nullptr, EAh, EAl, KP_X);

    // K5: posts = P1 @ W3^T + b3 -> fp32
    mma_gemm<0, 0><<<dim3(TB / 128, 1), 256>>>(
        EAh, EAl, KP_X, W3h, W3l, b3, 2 * S_DIM, posts, nullptr, nullptr, 0);

    // K6: sample
    const float* posts_last = posts + (size_t)(T_STEPS - 1) * B_DIM * 2 * S_DIM;
    sample_kernel<<<(B_DIM * S_DIM + 255) / 256, 256>>>(posts_last, sample);
}